// round 9
// baseline (speedup 1.0000x reference)
#include <cuda_runtime.h>
#include <cuda_bf16.h>
#include <cstdint>

static constexpr int B = 256;
static constexpr int D = 131072;
static constexpr long DL = D;

// Gram tiling: 64 K-slices x 2 row-halves = 128 CTAs
static constexpr int NSPLIT = 64;
static constexpr int KPC = D / NSPLIT;        // 2048 K per slice
static constexpr int KC = 32;                 // fp32 cols per chunk
static constexpr int NCHUNK = KPC / KC;       // 64
static constexpr int S = 4;                   // cp.async stages
static constexpr int STRIDE = 36;             // floats per smem row (pad: conflict-free)
static constexpr int STAGE_F = 256 * STRIDE;  // 9216 floats = 36864 B
static constexpr int SMEM_SZ = S * STAGE_F * 4;  // 147456 B

// ---------------- device scratch ----------------
__device__ float  g_Gpart[NSPLIT * B * B];    // 16 MB split-K partials
__device__ double g_G[B * B];
__device__ double g_rowsum[B];
__device__ unsigned long long g_rowmask[B * 4];
__device__ unsigned long long g_totalmask[4]; // OR is idempotent across replays
__device__ double g_f1[B];
__device__ double g_rowG[B];
__device__ float  g_pscale[2];

// ---------------- helpers ----------------
__device__ __forceinline__ uint32_t smem_u32(const void* p) {
    uint32_t a;
    asm("{ .reg .u64 t; cvta.to.shared.u64 t, %1; cvt.u32.u64 %0, t; }" : "=r"(a) : "l"(p));
    return a;
}
__device__ __forceinline__ void cp16(uint32_t saddr, const float* g) {
    asm volatile("cp.async.cg.shared.global [%0], [%1], 16;" :: "r"(saddr), "l"(g) : "memory");
}
#define CP_COMMIT() asm volatile("cp.async.commit_group;" ::: "memory")
#define CP_WAIT_S1() asm volatile("cp.async.wait_group %0;" :: "n"(S - 1) : "memory")

__device__ __forceinline__ void mma_tf32(float* c, const uint32_t* a, const uint32_t* b) {
    asm volatile(
        "mma.sync.aligned.m16n8k8.row.col.f32.tf32.tf32.f32 "
        "{%0,%1,%2,%3}, {%4,%5,%6,%7}, {%8,%9}, {%0,%1,%2,%3};"
        : "+f"(c[0]), "+f"(c[1]), "+f"(c[2]), "+f"(c[3])
        : "r"(a[0]), "r"(a[1]), "r"(a[2]), "r"(a[3]), "r"(b[0]), "r"(b[1]));
}

// ============================================================================
// Kernel 1: split-K Gram partials via mma.sync tf32.
// CTA (cl, h): K-slice [cl*2048, +2048), output rows [h*128, +128) x all 256.
// 8 warps: mw = wid>>2 (2 row blocks of 64), nw = wid&3 (4 col blocks of 64).
// ============================================================================
__global__ void __launch_bounds__(256, 1) gram_kernel(const float* __restrict__ x) {
    extern __shared__ float smem[];
    const uint32_t sb = smem_u32(smem);
    const int tid = threadIdx.x, wid = tid >> 5, lane = tid & 31;
    const int cl = blockIdx.x >> 1, h = blockIdx.x & 1;
    const long kbase = (long)cl * KPC;
    const int mw = wid >> 2, nw = wid & 3;
    const int aBase = h * 128 + mw * 64;
    const int nBase = nw * 64;
    const int lq = lane >> 2, lr = lane & 3;

    float acc[4][8][4];
    #pragma unroll
    for (int mb = 0; mb < 4; mb++)
        #pragma unroll
        for (int nb = 0; nb < 8; nb++)
            #pragma unroll
            for (int i = 0; i < 4; i++) acc[mb][nb][i] = 0.0f;

    // issue one 256x32 chunk (2048 x 16B) into stage s
    auto load_chunk = [&](int c, int s) {
        const float* gb = x + kbase + (long)c * KC;
        const uint32_t stage = sb + (uint32_t)(s * STAGE_F * 4);
        #pragma unroll
        for (int i = 0; i < 8; i++) {
            int sid = i * 256 + tid;
            int row = sid >> 3, c16 = sid & 7;
            cp16(stage + (uint32_t)(row * (STRIDE * 4) + c16 * 16),
                 gb + (long)row * DL + c16 * 4);
        }
        CP_COMMIT();
    };

    #pragma unroll
    for (int s = 0; s < S; s++) load_chunk(s, s);

    for (int c = 0; c < NCHUNK; c++) {
        const int st = c & (S - 1);
        CP_WAIT_S1();
        __syncthreads();
        const float* sp = smem + st * STAGE_F;
        #pragma unroll
        for (int ks = 0; ks < 4; ks++) {
            const int k0 = ks * 8 + lr;
            uint32_t a[4][4], bf[8][2];
            #pragma unroll
            for (int mb = 0; mb < 4; mb++) {
                const float* r0 = sp + (aBase + mb * 16 + lq) * STRIDE;
                a[mb][0] = __float_as_uint(r0[k0]);
                a[mb][1] = __float_as_uint(r0[8 * STRIDE + k0]);
                a[mb][2] = __float_as_uint(r0[k0 + 4]);
                a[mb][3] = __float_as_uint(r0[8 * STRIDE + k0 + 4]);
            }
            #pragma unroll
            for (int nb = 0; nb < 8; nb++) {
                const float* r0 = sp + (nBase + nb * 8 + lq) * STRIDE;
                bf[nb][0] = __float_as_uint(r0[k0]);
                bf[nb][1] = __float_as_uint(r0[k0 + 4]);
            }
            #pragma unroll
            for (int mb = 0; mb < 4; mb++)
                #pragma unroll
                for (int nb = 0; nb < 8; nb++) mma_tf32(acc[mb][nb], a[mb], bf[nb]);
        }
        __syncthreads();
        if (c + S < NCHUNK) load_chunk(c + S, st);
    }

    // write 128x256 partial: rows h*128.., all cols, into g_Gpart[cl]
    float* gp = g_Gpart + (size_t)cl * (B * B);
    #pragma unroll
    for (int mb = 0; mb < 4; mb++) {
        const int row0 = aBase + mb * 16 + lq;
        #pragma unroll
        for (int nb = 0; nb < 8; nb++) {
            const int col = nBase + nb * 8 + lr * 2;
            *reinterpret_cast<float2*>(gp + (size_t)row0 * B + col) =
                make_float2(acc[mb][nb][0], acc[mb][nb][1]);
            *reinterpret_cast<float2*>(gp + (size_t)(row0 + 8) * B + col) =
                make_float2(acc[mb][nb][2], acc[mb][nb][3]);
        }
    }
}

// ============================================================================
// Kernel 2: per-row sum (fp32 lane-split partials -> fp64 combine) +
// 256-bit rounded-value presence masks. grid 256 x 1024.
// ============================================================================
__global__ void __launch_bounds__(1024) stats_kernel(const float* __restrict__ x) {
    const int row = blockIdx.x;
    const float4* xr = reinterpret_cast<const float4*>(x + (size_t)row * D);
    __shared__ double ssum[32];
    __shared__ unsigned long long smk[4];
    if (threadIdx.x < 4) smk[threadIdx.x] = 0ull;
    __syncthreads();

    float s0 = 0.f, s1 = 0.f, s2 = 0.f, s3 = 0.f;
    unsigned long long m0 = 0, m1 = 0, m2 = 0, m3 = 0;
    #pragma unroll 4
    for (int q = 0; q < D / 4 / 1024; ++q) {
        float4 v = xr[(size_t)q * 1024 + threadIdx.x];
        s0 += v.x; s1 += v.y; s2 += v.z; s3 += v.w;
        float vals[4] = {v.x, v.y, v.z, v.w};
        #pragma unroll
        for (int t = 0; t < 4; t++) {
            int iv = __float2int_rn(vals[t]) + 128;  // rn = half-to-even = jnp.round
            iv = max(0, min(255, iv));
            unsigned long long bit = 1ull << (iv & 63);
            int w = iv >> 6;
            if (w == 0) m0 |= bit; else if (w == 1) m1 |= bit;
            else if (w == 2) m2 |= bit; else m3 |= bit;
        }
    }
    double sum = ((double)s0 + (double)s1) + ((double)s2 + (double)s3);
    #pragma unroll
    for (int o = 16; o; o >>= 1) {
        sum += __shfl_xor_sync(0xffffffffu, sum, o);
        m0 |= __shfl_xor_sync(0xffffffffu, m0, o);
        m1 |= __shfl_xor_sync(0xffffffffu, m1, o);
        m2 |= __shfl_xor_sync(0xffffffffu, m2, o);
        m3 |= __shfl_xor_sync(0xffffffffu, m3, o);
    }
    const int wd = threadIdx.x >> 5, li = threadIdx.x & 31;
    if (li == 0) {
        ssum[wd] = sum;
        atomicOr(&smk[0], m0); atomicOr(&smk[1], m1);
        atomicOr(&smk[2], m2); atomicOr(&smk[3], m3);
    }
    __syncthreads();
    if (threadIdx.x < 32) {
        double t = ssum[threadIdx.x];
        #pragma unroll
        for (int o = 16; o; o >>= 1) t += __shfl_xor_sync(0xffffffffu, t, o);
        if (threadIdx.x == 0) g_rowsum[row] = t;
    }
    if (threadIdx.x < 4) {
        unsigned long long mm = smk[threadIdx.x];
        g_rowmask[row * 4 + threadIdx.x] = mm;
        atomicOr(&g_totalmask[threadIdx.x], mm);
    }
}

// Kernel 3: deterministic split-K reduce -> g_G (double). grid 256 x 256.
__global__ void __launch_bounds__(256) reduce_g_kernel() {
    const int e = blockIdx.x * 256 + threadIdx.x;
    double s = 0.0;
    #pragma unroll 8
    for (int cl = 0; cl < NSPLIT; cl++) s += (double)g_Gpart[(size_t)cl * (B * B) + e];
    g_G[e] = s;
}

// Kernel 4: factor1 (mean |clipped corr|) + rowG. grid 256 x 256.
__global__ void __launch_bounds__(256) corr_kernel() {
    const int i = blockIdx.x, j = threadIdx.x;
    const double Dd = (double)D, dinv = 1.0 / (Dd - 1.0);
    double Gij = g_G[i * B + j], Gii = g_G[i * B + i], Gjj = g_G[j * B + j];
    double mui = g_rowsum[i] / Dd, muj = g_rowsum[j] / Dd;
    double cii = (Gii - Dd * mui * mui) * dinv;
    double cjj = (Gjj - Dd * muj * muj) * dinv;
    double cij = (Gij - Dd * mui * muj) * dinv;
    double c = fmin(fabs(cij) / sqrt(cii * cjj), 1.0);
    __shared__ double r1[256], r2[256];
    r1[j] = c; r2[j] = Gij;
    __syncthreads();
    for (int o = 128; o; o >>= 1) {
        if (j < o) { r1[j] += r1[j + o]; r2[j] += r2[j + o]; }
        __syncthreads();
    }
    if (j == 0) { g_f1[i] = r1[0] / (double)B; g_rowG[i] = r2[0]; }
}

// Kernel 5: p = max(max candidates, 0); scale = 1/(1-p). 1 x 256.
__global__ void __launch_bounds__(256) finalize_kernel() {
    const int i = threadIdx.x;
    __shared__ double sh[256];
    const double Bd = (double)B;

    double rowG = g_rowG[i];
    sh[i] = rowG; __syncthreads();
    for (int o = 128; o; o >>= 1) { if (i < o) sh[i] += sh[i + o]; __syncthreads(); }
    const double Stot = sh[0];
    __syncthreads();

    double Gii = g_G[i * B + i];
    double mse = Gii - 2.0 * rowG / Bd + Stot / (Bd * Bd);  // row_mse * D (D cancels in ratio)
    sh[i] = mse; __syncthreads();
    for (int o = 128; o; o >>= 1) { if (i < o) sh[i] += sh[i + o]; __syncthreads(); }
    const double total = sh[0];
    __syncthreads();

    int ru = 0, tu = 0;
    #pragma unroll
    for (int w = 0; w < 4; w++) {
        ru += __popcll(g_rowmask[i * 4 + w]);
        tu += __popcll(g_totalmask[w]);
    }
    double f2 = mse / total;
    double f3 = (double)((float)ru / (float)tu);
    double cand = (1.0 - g_f1[i]) * f2 * f3;
    sh[i] = cand; __syncthreads();
    for (int o = 128; o; o >>= 1) { if (i < o) sh[i] = fmax(sh[i], sh[i + o]); __syncthreads(); }
    if (i == 0) {
        double p = fmax(sh[0], 0.0);
        g_pscale[0] = (float)p;
        g_pscale[1] = (float)(1.0 / (1.0 - p));
    }
}

// Kernel 6: out = x * (noise >= p) / (1-p). grid 8192 x 1024, float4.
__global__ void __launch_bounds__(1024) dropout_kernel(const float4* __restrict__ x,
                                                       const float4* __restrict__ nz,
                                                       float4* __restrict__ out) {
    const float p = g_pscale[0], sc = g_pscale[1];
    const size_t idx = (size_t)blockIdx.x * 1024 + threadIdx.x;
    float4 v = x[idx], n = nz[idx], o;
    o.x = (n.x >= p) ? v.x * sc : 0.0f;
    o.y = (n.y >= p) ? v.y * sc : 0.0f;
    o.z = (n.z >= p) ? v.z * sc : 0.0f;
    o.w = (n.w >= p) ? v.w * sc : 0.0f;
    out[idx] = o;
}

extern "C" void kernel_launch(void* const* d_in, const int* in_sizes, int n_in,
                              void* d_out, int out_size) {
    const float* x  = (const float*)d_in[0];
    const float* nz = (const float*)d_in[1];
    float* out = (float*)d_out;
    (void)in_sizes; (void)n_in; (void)out_size;

    cudaFuncSetAttribute(gram_kernel, cudaFuncAttributeMaxDynamicSharedMemorySize, SMEM_SZ);
    gram_kernel<<<NSPLIT * 2, 256, SMEM_SZ>>>(x);
    stats_kernel<<<B, 1024>>>(x);
    reduce_g_kernel<<<B, 256>>>();
    corr_kernel<<<B, 256>>>();
    finalize_kernel<<<1, 256>>>();
    dropout_kernel<<<(B * D) / 4 / 1024, 1024>>>((const float4*)x, (const float4*)nz,
                                                 (float4*)out);
}

// round 10
// speedup vs baseline: 1.2231x; 1.2231x over previous
#include <cuda_runtime.h>
#include <cuda_bf16.h>
#include <cstdint>

static constexpr int B = 256;
static constexpr int D = 131072;
static constexpr long DL = D;

// Gram tiling: 64 K-slices x 2 row-halves = 128 CTAs, bf16 operands
static constexpr int NSPLIT = 64;
static constexpr int KPC = D / NSPLIT;        // 2048 K per slice
static constexpr int KC = 64;                 // bf16 cols per chunk (128 B row)
static constexpr int NCHUNK = KPC / KC;       // 32
static constexpr int S = 4;                   // cp.async stages
static constexpr int ROW_B = 144;             // bytes per smem row (128 data + 16 pad)
static constexpr int ROW_W = ROW_B / 4;       // 36 u32 (4 mod 32 -> conflict-free frags)
static constexpr int STAGE_B = 256 * ROW_B;   // 36864 B
static constexpr int SMEM_SZ = S * STAGE_B;   // 147456 B

// ---------------- device scratch ----------------
__device__ __nv_bfloat16 g_xh[(size_t)B * D];   // 64 MB bf16 copy of x
__device__ float  g_Gpart[NSPLIT * B * B];      // 16 MB split-K partials
__device__ double g_G[B * B];
__device__ double g_rowsum[B];
__device__ double g_mu[B];
__device__ double g_invstd[B];
__device__ unsigned long long g_rowmask[B * 4];
__device__ unsigned long long g_totalmask[4];   // OR is idempotent across replays
__device__ double g_f1[B];
__device__ double g_rowG[B];
__device__ float  g_pscale[2];

// ---------------- helpers ----------------
__device__ __forceinline__ uint32_t smem_u32(const void* p) {
    uint32_t a;
    asm("{ .reg .u64 t; cvta.to.shared.u64 t, %1; cvt.u32.u64 %0, t; }" : "=r"(a) : "l"(p));
    return a;
}
__device__ __forceinline__ void cp16(uint32_t saddr, const void* g) {
    asm volatile("cp.async.cg.shared.global [%0], [%1], 16;" :: "r"(saddr), "l"(g) : "memory");
}
#define CP_COMMIT() asm volatile("cp.async.commit_group;" ::: "memory")
#define CP_WAIT_S1() asm volatile("cp.async.wait_group %0;" :: "n"(S - 1) : "memory")

__device__ __forceinline__ void mma_bf16(float* c, const uint32_t* a, const uint32_t* b) {
    asm volatile(
        "mma.sync.aligned.m16n8k16.row.col.f32.bf16.bf16.f32 "
        "{%0,%1,%2,%3}, {%4,%5,%6,%7}, {%8,%9}, {%0,%1,%2,%3};"
        : "+f"(c[0]), "+f"(c[1]), "+f"(c[2]), "+f"(c[3])
        : "r"(a[0]), "r"(a[1]), "r"(a[2]), "r"(a[3]), "r"(b[0]), "r"(b[1]));
}

// ============================================================================
// Kernel 1: per-row sum + 256-bit rounded-value presence masks + bf16 copy.
// grid 256 x 1024, float4 loads.
// ============================================================================
__global__ void __launch_bounds__(1024) stats_kernel(const float* __restrict__ x) {
    const int row = blockIdx.x;
    const float4* xr = reinterpret_cast<const float4*>(x + (size_t)row * D);
    uint2* xh = reinterpret_cast<uint2*>(g_xh + (size_t)row * D);
    __shared__ double ssum[32];
    __shared__ unsigned long long smk[4];
    if (threadIdx.x < 4) smk[threadIdx.x] = 0ull;
    __syncthreads();

    float s0 = 0.f, s1 = 0.f, s2 = 0.f, s3 = 0.f;
    unsigned long long m0 = 0, m1 = 0, m2 = 0, m3 = 0;
    #pragma unroll 4
    for (int q = 0; q < D / 4 / 1024; ++q) {
        const size_t idx = (size_t)q * 1024 + threadIdx.x;
        float4 v = xr[idx];
        s0 += v.x; s1 += v.y; s2 += v.z; s3 += v.w;
        __nv_bfloat162 h01 = __floats2bfloat162_rn(v.x, v.y);
        __nv_bfloat162 h23 = __floats2bfloat162_rn(v.z, v.w);
        uint2 packed;
        packed.x = *reinterpret_cast<uint32_t*>(&h01);
        packed.y = *reinterpret_cast<uint32_t*>(&h23);
        xh[idx] = packed;
        float vals[4] = {v.x, v.y, v.z, v.w};
        #pragma unroll
        for (int t = 0; t < 4; t++) {
            int iv = __float2int_rn(vals[t]) + 128;  // rn = half-to-even = jnp.round
            iv = max(0, min(255, iv));
            unsigned long long bit = 1ull << (iv & 63);
            int w = iv >> 6;
            if (w == 0) m0 |= bit; else if (w == 1) m1 |= bit;
            else if (w == 2) m2 |= bit; else m3 |= bit;
        }
    }
    double sum = ((double)s0 + (double)s1) + ((double)s2 + (double)s3);
    #pragma unroll
    for (int o = 16; o; o >>= 1) {
        sum += __shfl_xor_sync(0xffffffffu, sum, o);
        m0 |= __shfl_xor_sync(0xffffffffu, m0, o);
        m1 |= __shfl_xor_sync(0xffffffffu, m1, o);
        m2 |= __shfl_xor_sync(0xffffffffu, m2, o);
        m3 |= __shfl_xor_sync(0xffffffffu, m3, o);
    }
    const int wd = threadIdx.x >> 5, li = threadIdx.x & 31;
    if (li == 0) {
        ssum[wd] = sum;
        atomicOr(&smk[0], m0); atomicOr(&smk[1], m1);
        atomicOr(&smk[2], m2); atomicOr(&smk[3], m3);
    }
    __syncthreads();
    if (threadIdx.x < 32) {
        double t = ssum[threadIdx.x];
        #pragma unroll
        for (int o = 16; o; o >>= 1) t += __shfl_xor_sync(0xffffffffu, t, o);
        if (threadIdx.x == 0) g_rowsum[row] = t;
    }
    if (threadIdx.x < 4) {
        unsigned long long mm = smk[threadIdx.x];
        g_rowmask[row * 4 + threadIdx.x] = mm;
        atomicOr(&g_totalmask[threadIdx.x], mm);
    }
}

// ============================================================================
// Kernel 2: split-K Gram partials via mma.sync m16n8k16 bf16.
// CTA (cl, h): K-slice [cl*2048, +2048), output rows [h*128, +128) x all 256.
// 8 warps: mw = wid>>2 (2 row blocks of 64), nw = wid&3 (4 col blocks of 64).
// ============================================================================
__global__ void __launch_bounds__(256, 1) gram_kernel() {
    extern __shared__ char smem[];
    const uint32_t sb = smem_u32(smem);
    const int tid = threadIdx.x, wid = tid >> 5, lane = tid & 31;
    const int cl = blockIdx.x >> 1, h = blockIdx.x & 1;
    const long kbase = (long)cl * KPC;
    const int mw = wid >> 2, nw = wid & 3;
    const int aBase = h * 128 + mw * 64;
    const int nBase = nw * 64;
    const int lq = lane >> 2, lr = lane & 3;

    float acc[4][8][4];
    #pragma unroll
    for (int mb = 0; mb < 4; mb++)
        #pragma unroll
        for (int nb = 0; nb < 8; nb++)
            #pragma unroll
            for (int i = 0; i < 4; i++) acc[mb][nb][i] = 0.0f;

    // issue one 256x64 bf16 chunk (2048 x 16B) into stage s
    auto load_chunk = [&](int c, int s) {
        const __nv_bfloat16* gb = g_xh + kbase + (long)c * KC;
        const uint32_t stage = sb + (uint32_t)(s * STAGE_B);
        #pragma unroll
        for (int i = 0; i < 8; i++) {
            int sid = i * 256 + tid;
            int row = sid >> 3, c16 = sid & 7;
            cp16(stage + (uint32_t)(row * ROW_B + c16 * 16),
                 gb + (long)row * DL + c16 * 8);
        }
        CP_COMMIT();
    };

    #pragma unroll
    for (int s = 0; s < S; s++) load_chunk(s, s);

    for (int c = 0; c < NCHUNK; c++) {
        const int st = c & (S - 1);
        CP_WAIT_S1();
        __syncthreads();
        const uint32_t* sp = reinterpret_cast<const uint32_t*>(smem + st * STAGE_B);
        #pragma unroll
        for (int ks = 0; ks < 4; ks++) {
            const int koff = ks * 8 + lr;          // u32 index within 32-word row
            uint32_t a[4][4], bf[8][2];
            #pragma unroll
            for (int mb = 0; mb < 4; mb++) {
                const uint32_t* r0 = sp + (aBase + mb * 16 + lq) * ROW_W;
                a[mb][0] = r0[koff];
                a[mb][1] = r0[8 * ROW_W + koff];
                a[mb][2] = r0[koff + 4];
                a[mb][3] = r0[8 * ROW_W + koff + 4];
            }
            #pragma unroll
            for (int nb = 0; nb < 8; nb++) {
                const uint32_t* r0 = sp + (nBase + nb * 8 + lq) * ROW_W;
                bf[nb][0] = r0[koff];
                bf[nb][1] = r0[koff + 4];
            }
            #pragma unroll
            for (int mb = 0; mb < 4; mb++)
                #pragma unroll
                for (int nb = 0; nb < 8; nb++) mma_bf16(acc[mb][nb], a[mb], bf[nb]);
        }
        __syncthreads();
        if (c + S < NCHUNK) load_chunk(c + S, st);
    }

    // write 128x256 partial: rows h*128.., all cols, into g_Gpart[cl]
    float* gp = g_Gpart + (size_t)cl * (B * B);
    #pragma unroll
    for (int mb = 0; mb < 4; mb++) {
        const int row0 = aBase + mb * 16 + lq;
        #pragma unroll
        for (int nb = 0; nb < 8; nb++) {
            const int col = nBase + nb * 8 + lr * 2;
            *reinterpret_cast<float2*>(gp + (size_t)row0 * B + col) =
                make_float2(acc[mb][nb][0], acc[mb][nb][1]);
            *reinterpret_cast<float2*>(gp + (size_t)(row0 + 8) * B + col) =
                make_float2(acc[mb][nb][2], acc[mb][nb][3]);
        }
    }
}

// Kernel 3: deterministic split-K reduce -> g_G (double). grid 256 x 256.
__global__ void __launch_bounds__(256) reduce_g_kernel() {
    const int e = blockIdx.x * 256 + threadIdx.x;
    double s = 0.0;
    #pragma unroll 8
    for (int cl = 0; cl < NSPLIT; cl++) s += (double)g_Gpart[(size_t)cl * (B * B) + e];
    g_G[e] = s;
}

// Kernel 4: per-row mu and 1/sqrt(cov_ii). 1 x 256.
__global__ void __launch_bounds__(256) prep_kernel() {
    const int i = threadIdx.x;
    const double Dd = (double)D, dinv = 1.0 / (Dd - 1.0);
    double mu = g_rowsum[i] / Dd;
    double cii = (g_G[i * B + i] - Dd * mu * mu) * dinv;
    g_mu[i] = mu;
    g_invstd[i] = 1.0 / sqrt(cii);
}

// Kernel 5: factor1 (mean |clipped corr|) + rowG. grid 256 x 256.
__global__ void __launch_bounds__(256) corr_kernel() {
    const int i = blockIdx.x, j = threadIdx.x;
    const double Dd = (double)D, dinv = 1.0 / (Dd - 1.0);
    double Gij = g_G[i * B + j];
    double cij = (Gij - Dd * g_mu[i] * g_mu[j]) * dinv;
    double c = fmin(fabs(cij) * g_invstd[i] * g_invstd[j], 1.0);
    __shared__ double r1[256], r2[256];
    r1[j] = c; r2[j] = Gij;
    __syncthreads();
    for (int o = 128; o; o >>= 1) {
        if (j < o) { r1[j] += r1[j + o]; r2[j] += r2[j + o]; }
        __syncthreads();
    }
    if (j == 0) { g_f1[i] = r1[0] / (double)B; g_rowG[i] = r2[0]; }
}

// Kernel 6: p = max(max candidates, 0); scale = 1/(1-p). 1 x 256.
__global__ void __launch_bounds__(256) finalize_kernel() {
    const int i = threadIdx.x;
    __shared__ double sh[256];
    const double Bd = (double)B;

    double rowG = g_rowG[i];
    sh[i] = rowG; __syncthreads();
    for (int o = 128; o; o >>= 1) { if (i < o) sh[i] += sh[i + o]; __syncthreads(); }
    const double Stot = sh[0];
    __syncthreads();

    double Gii = g_G[i * B + i];
    double mse = Gii - 2.0 * rowG / Bd + Stot / (Bd * Bd);  // row_mse * D (D cancels in ratio)
    sh[i] = mse; __syncthreads();
    for (int o = 128; o; o >>= 1) { if (i < o) sh[i] += sh[i + o]; __syncthreads(); }
    const double total = sh[0];
    __syncthreads();

    int ru = 0, tu = 0;
    #pragma unroll
    for (int w = 0; w < 4; w++) {
        ru += __popcll(g_rowmask[i * 4 + w]);
        tu += __popcll(g_totalmask[w]);
    }
    double f2 = mse / total;
    double f3 = (double)((float)ru / (float)tu);
    double cand = (1.0 - g_f1[i]) * f2 * f3;
    sh[i] = cand; __syncthreads();
    for (int o = 128; o; o >>= 1) { if (i < o) sh[i] = fmax(sh[i], sh[i + o]); __syncthreads(); }
    if (i == 0) {
        double p = fmax(sh[0], 0.0);
        g_pscale[0] = (float)p;
        g_pscale[1] = (float)(1.0 / (1.0 - p));
    }
}

// Kernel 7: out = x * (noise >= p) / (1-p). grid 8192 x 1024, float4.
__global__ void __launch_bounds__(1024) dropout_kernel(const float4* __restrict__ x,
                                                       const float4* __restrict__ nz,
                                                       float4* __restrict__ out) {
    const float p = g_pscale[0], sc = g_pscale[1];
    const size_t idx = (size_t)blockIdx.x * 1024 + threadIdx.x;
    float4 v = x[idx], n = nz[idx], o;
    o.x = (n.x >= p) ? v.x * sc : 0.0f;
    o.y = (n.y >= p) ? v.y * sc : 0.0f;
    o.z = (n.z >= p) ? v.z * sc : 0.0f;
    o.w = (n.w >= p) ? v.w * sc : 0.0f;
    out[idx] = o;
}

extern "C" void kernel_launch(void* const* d_in, const int* in_sizes, int n_in,
                              void* d_out, int out_size) {
    const float* x  = (const float*)d_in[0];
    const float* nz = (const float*)d_in[1];
    float* out = (float*)d_out;
    (void)in_sizes; (void)n_in; (void)out_size;

    cudaFuncSetAttribute(gram_kernel, cudaFuncAttributeMaxDynamicSharedMemorySize, SMEM_SZ);
    stats_kernel<<<B, 1024>>>(x);
    gram_kernel<<<NSPLIT * 2, 256, SMEM_SZ>>>();
    reduce_g_kernel<<<B, 256>>>();
    prep_kernel<<<1, 256>>>();
    corr_kernel<<<B, 256>>>();
    finalize_kernel<<<1, 256>>>();
    dropout_kernel<<<(B * D) / 4 / 1024, 1024>>>((const float4*)x, (const float4*)nz,
                                                 (float4*)out);
}